// round 15
// baseline (speedup 1.0000x reference)
#include <cuda_runtime.h>
#include <math.h>

#define BB 8
#define TT 1024
#define DD 128
#define UU 2048
#define OUTF (DD + UU)
#define NCTA 128
#define COLS 16
#define NTHR 512
#define NWARP 16

typedef unsigned long long ull;

// SMEM layout (floats) — no state staging (L2-direct reads)
#define W_FLOATS   (UU * COLS)    // 32768  w_res slice, 64B rows, chunk-swizzled
#define WI_FLOATS  (DD * COLS)    // 2048   w_in slice, same swizzle
#define BI_FLOATS  16
#define MASK_FLOATS 4
#define RED_ULL    (NWARP * 64)   // [16 warps][64 og] f32x2 partials
#define SMEM_FLOATS (W_FLOATS + WI_FLOATS + BI_FLOATS + MASK_FLOATS + RED_ULL * 2)
#define SMEM_BYTES  (SMEM_FLOATS * 4)   // ~147 KB

__device__ float g_state[2][UU * BB];   // ping-pong state, linear [k][b]
__device__ unsigned g_bar_count;        // init barrier
__device__ unsigned g_bar_gen;          // monotone across replays
__device__ unsigned g_cnt[4 * 64];      // per-group step counters, 256B apart

// packed fp32x2 ops — ptxas never emits these from C++
__device__ __forceinline__ void ffma2(ull& acc, ull a, ull b) {
    asm("fma.rn.f32x2 %0, %1, %2, %0;" : "+l"(acc) : "l"(a), "l"(b));
}
__device__ __forceinline__ ull dup2(float x) {
    ull r;
    unsigned xi = __float_as_uint(x);
    asm("mov.b64 %0, {%1, %1};" : "=l"(r) : "r"(xi));
    return r;
}
__device__ __forceinline__ ull padd2(ull a, ull b) {
    ull r;
    asm("add.rn.f32x2 %0, %1, %2;" : "=l"(r) : "l"(a), "l"(b));
    return r;
}
__device__ __forceinline__ ull bfly2(ull v, int m) {
    unsigned lo = (unsigned)v, hi = (unsigned)(v >> 32);
    lo = __shfl_xor_sync(0xffffffffu, lo, m);
    hi = __shfl_xor_sync(0xffffffffu, hi, m);
    ull r;
    asm("mov.b64 %0, {%1, %2};" : "=l"(r) : "r"(lo), "r"(hi));
    return r;
}
__device__ __forceinline__ unsigned acq(const unsigned* p) {
    unsigned v;
    asm volatile("ld.acquire.gpu.global.u32 %0, [%1];" : "=r"(v) : "l"(p));
    return v;
}
// fast tanh: clamp + expf (MUFU.EX2 chain), rel err ~1e-6
__device__ __forceinline__ float ftanh(float x) {
    float xc = fminf(fmaxf(x, -10.f), 10.f);
    float e = __expf(2.f * xc);
    return 1.f - __fdividef(2.f, e + 1.f);
}

// init-only grid barrier (proven pattern)
__device__ __forceinline__ void grid_barrier_init() {
    __syncthreads();
    if (threadIdx.x == 0) {
        __threadfence();
        unsigned gen;
        asm volatile("ld.acquire.gpu.u32 %0, [%1];" : "=r"(gen) : "l"(&g_bar_gen));
        if (atomicAdd(&g_bar_count, 1) == NCTA - 1) {
            g_bar_count = 0;
            asm volatile("st.release.gpu.u32 [%0], %1;" :: "l"(&g_bar_gen), "r"(gen + 1)
                         : "memory");
        } else {
            unsigned cur;
            do {
                asm volatile("ld.acquire.gpu.u32 %0, [%1];" : "=r"(cur) : "l"(&g_bar_gen));
                if (cur != gen) break;
                __nanosleep(32);
            } while (true);
        }
    }
    __syncthreads();
}

__global__ void __launch_bounds__(NTHR, 1)
esn_kernel(const float* __restrict__ inputs, const float* __restrict__ w_in_g,
           const float* __restrict__ b_in_g, const float* __restrict__ w_res_g,
           float* __restrict__ out) {
    extern __shared__ float smem[];
    float* w_sh  = smem;                    // [2048][16] chunk-swizzled
    float* wi_sh = w_sh + W_FLOATS;         // [128][16] chunk-swizzled
    float* bi_sh = wi_sh + WI_FLOATS;       // [16]
    unsigned* mask_sh = (unsigned*)(bi_sh + BI_FLOATS);
    ull* red = (ull*)(bi_sh + BI_FLOATS + MASK_FLOATS);   // [16 warps][64]

    const int tid = threadIdx.x;
    const int cta = blockIdx.x;
    const int col0 = cta * COLS;
    const int grp = cta >> 5;               // producer group (chunk) 0..3

    if (cta == 0 && tid == 0) {             // fresh epoch per launch/replay
        g_cnt[0] = 0; g_cnt[64] = 0; g_cnt[128] = 0; g_cnt[192] = 0;
    }

    // Stage w_res slice; 16B chunk c of row r stored at position c ^ ((r>>1)&3)
    for (int r = tid; r < UU; r += NTHR) {
        const float4* src = (const float4*)(w_res_g + (size_t)r * UU + col0);
        int m = (r >> 1) & 3;
        float4* dst = (float4*)(w_sh + r * COLS);
        dst[0 ^ m] = src[0]; dst[1 ^ m] = src[1];
        dst[2 ^ m] = src[2]; dst[3 ^ m] = src[3];
    }
    if (tid < DD) {
        int r = tid;
        const float4* src = (const float4*)(w_in_g + (size_t)r * UU + col0);
        int m = (r >> 1) & 3;
        float4* dst = (float4*)(wi_sh + r * COLS);
        dst[0 ^ m] = src[0]; dst[1 ^ m] = src[1];
        dst[2 ^ m] = src[2]; dst[3 ^ m] = src[3];
    }
    if (tid < COLS) bi_sh[tid] = b_in_g[col0 + tid];

    // Zero initial state (buffer 0)
    for (int i = cta * NTHR + tid; i < UU * BB; i += NCTA * NTHR) g_state[0][i] = 0.0f;

    grid_barrier_init();

    // Decomposition: paired lanes share a k-slice; jh = column half (8 cols).
    const int warp = tid >> 5;
    const int lane = tid & 31;
    const int jh = lane & 1;
    const int ks = (warp << 4) + (lane >> 1);     // 0..255
    const int mk = (ks >> 1) & 3;                 // weight chunk-swizzle key
    const unsigned w_off0 = (unsigned)(4 * ks + ((2 * jh) ^ mk)) * 16;
    const unsigned w_off1 = (unsigned)(4 * ks + ((2 * jh + 1) ^ mk)) * 16;
    // butterfly landing map: lane bit1->+16, bit2->+8, bit3->+4, bit4->+2
    const int base = (((lane >> 1) & 1) << 4) | (((lane >> 2) & 1) << 3) |
                     (((lane >> 3) & 1) << 2) | (((lane >> 4) & 1) << 1);

    for (int t = 0; t < TT; ++t) {
        // x_t for proj rows (ks<128): in flight over the entry gate
        float xv[8];
        if (ks < DD) {
#pragma unroll
            for (int b = 0; b < 8; ++b)
                xv[b] = __ldg(inputs + ((size_t)(b * TT + t)) * DD + ks);
        }

        // Entry gate: wait ONLY for own group's 32 producers; snapshot the rest.
        const unsigned tgt = 32u * (unsigned)t;
        if (tid == 0) {
            while (acq(&g_cnt[grp * 64]) < tgt) {}
            unsigned m = 1u << grp;
            unsigned v0 = acq(&g_cnt[0]);
            unsigned v1 = acq(&g_cnt[64]);
            unsigned v2 = acq(&g_cnt[128]);
            unsigned v3 = acq(&g_cnt[192]);
            if (v0 >= tgt) m |= 1u;
            if (v1 >= tgt) m |= 2u;
            if (v2 >= tgt) m |= 4u;
            if (v3 >= tgt) m |= 8u;
            *mask_sh = m;
        }
        __syncthreads();
        const unsigned mask = *mask_sh;

        // L2-direct state: row ks+256i at float4 index 2ks+512i. Chunk c = rows
        // [512c,512c+512) = i in {2c, 2c+1}. Double-buffered, 1 chunk lookahead.
        const float4* sp = (const float4*)(g_state[t & 1]) + 2 * ks;
        float4 sA[2][2], sB[2][2];
        {   // prefetch chunk cs[0] = grp (gated by entry)
            const float4* q = sp + 1024 * grp;
            sA[0][0] = __ldcg(q);       sB[0][0] = __ldcg(q + 1);
            sA[0][1] = __ldcg(q + 512); sB[0][1] = __ldcg(q + 513);
        }

        ull acc[8][4];
#pragma unroll
        for (int a1 = 0; a1 < 8; ++a1)
#pragma unroll
            for (int a2 = 0; a2 < 4; ++a2) acc[a1][a2] = 0ULL;

        // Input projection (covers first chunk's L2 latency)
        if (ks < DD) {
            ulonglong2 u0 = *(const ulonglong2*)((const char*)wi_sh + w_off0);
            ulonglong2 u1 = *(const ulonglong2*)((const char*)wi_sh + w_off1);
#pragma unroll
            for (int b = 0; b < 8; ++b) {
                ull d = dup2(xv[b]);
                ffma2(acc[b][0], u0.x, d); ffma2(acc[b][1], u0.y, d);
                ffma2(acc[b][2], u1.x, d); ffma2(acc[b][3], u1.y, d);
            }
        }

#pragma unroll
        for (int j = 0; j < 4; ++j) {
            const int buf = j & 1;
            const int c = (grp + j) & 3;
            if (j < 3) {
                const int cn = (grp + j + 1) & 3;
                if (!((mask >> cn) & 1)) {
                    // late producer group: just-in-time gate (uniform branch)
                    if (tid == 0) { while (acq(&g_cnt[cn * 64]) < tgt) {} }
                    __syncthreads();
                }
                const float4* q = sp + 1024 * cn;   // prefetch next chunk
                sA[buf ^ 1][0] = __ldcg(q);       sB[buf ^ 1][0] = __ldcg(q + 1);
                sA[buf ^ 1][1] = __ldcg(q + 512); sB[buf ^ 1][1] = __ldcg(q + 513);
            }
#pragma unroll
            for (int p2 = 0; p2 < 2; ++p2) {
                const int i = 2 * c + p2;
                float4 vA = sA[buf][p2];
                float4 vB = sB[buf][p2];
                ulonglong2 u0 = *(const ulonglong2*)((const char*)w_sh + w_off0 + i * 16384);
                ulonglong2 u1 = *(const ulonglong2*)((const char*)w_sh + w_off1 + i * 16384);
                ull d;
                d = dup2(vA.x);
                ffma2(acc[0][0], u0.x, d); ffma2(acc[0][1], u0.y, d);
                ffma2(acc[0][2], u1.x, d); ffma2(acc[0][3], u1.y, d);
                d = dup2(vA.y);
                ffma2(acc[1][0], u0.x, d); ffma2(acc[1][1], u0.y, d);
                ffma2(acc[1][2], u1.x, d); ffma2(acc[1][3], u1.y, d);
                d = dup2(vA.z);
                ffma2(acc[2][0], u0.x, d); ffma2(acc[2][1], u0.y, d);
                ffma2(acc[2][2], u1.x, d); ffma2(acc[2][3], u1.y, d);
                d = dup2(vA.w);
                ffma2(acc[3][0], u0.x, d); ffma2(acc[3][1], u0.y, d);
                ffma2(acc[3][2], u1.x, d); ffma2(acc[3][3], u1.y, d);
                d = dup2(vB.x);
                ffma2(acc[4][0], u0.x, d); ffma2(acc[4][1], u0.y, d);
                ffma2(acc[4][2], u1.x, d); ffma2(acc[4][3], u1.y, d);
                d = dup2(vB.y);
                ffma2(acc[5][0], u0.x, d); ffma2(acc[5][1], u0.y, d);
                ffma2(acc[5][2], u1.x, d); ffma2(acc[5][3], u1.y, d);
                d = dup2(vB.z);
                ffma2(acc[6][0], u0.x, d); ffma2(acc[6][1], u0.y, d);
                ffma2(acc[6][2], u1.x, d); ffma2(acc[6][3], u1.y, d);
                d = dup2(vB.w);
                ffma2(acc[7][0], u0.x, d); ffma2(acc[7][1], u0.y, d);
                ffma2(acc[7][2], u1.x, d); ffma2(acc[7][3], u1.y, d);
            }
        }

        // 4-level butterfly over masks 2,4,8,16 (mask-1 partner owns the other
        // column half, not summed). Lane ends with og (jh, base), (jh, base+1).
        {
            ull* A = &acc[0][0];
#pragma unroll
            for (int lev = 0; lev < 4; ++lev) {
                const int mm = 2 << lev;
                const int n = 16 >> lev;
                const bool up = (lane & mm) != 0;
#pragma unroll
                for (int q = 0; q < n; ++q) {
                    ull send = up ? A[q] : A[q + n];
                    ull recv = bfly2(send, mm);
                    ull keep = up ? A[q + n] : A[q];
                    A[q] = padd2(keep, recv);
                }
            }
            red[warp * 64 + jh * 32 + base] = A[0];
            red[warp * 64 + jh * 32 + base + 1] = A[1];
        }
        __syncthreads();

        // Final reduce (tree) + epilogue (64 threads). Others run ahead to t+1's
        // entry gate; red overwrites for t+1 happen only after the entry sync,
        // which tid0 (an epilogue thread) reaches after epilogue + release.
        if (tid < 64) {
            ull r0 = padd2(red[tid],            red[64 + tid]);
            ull r1 = padd2(red[2 * 64 + tid],   red[3 * 64 + tid]);
            ull r2 = padd2(red[4 * 64 + tid],   red[5 * 64 + tid]);
            ull r3 = padd2(red[6 * 64 + tid],   red[7 * 64 + tid]);
            ull r4 = padd2(red[8 * 64 + tid],   red[9 * 64 + tid]);
            ull r5 = padd2(red[10 * 64 + tid],  red[11 * 64 + tid]);
            ull r6 = padd2(red[12 * 64 + tid],  red[13 * 64 + tid]);
            ull r7 = padd2(red[14 * 64 + tid],  red[15 * 64 + tid]);
            r0 = padd2(r0, r1); r2 = padd2(r2, r3);
            r4 = padd2(r4, r5); r6 = padd2(r6, r7);
            r0 = padd2(r0, r2); r4 = padd2(r4, r6);
            ull v = padd2(r0, r4);
            const int jh2 = tid >> 5;
            const int a = tid & 31;
            const int b = a >> 2;
            const int p = a & 3;
            const int jl = jh2 * 8 + 2 * p;
            const int c0 = col0 + jl;
            float pre0 = __uint_as_float((unsigned)v) + bi_sh[jl];
            float pre1 = __uint_as_float((unsigned)(v >> 32)) + bi_sh[jl + 1];
            const float* sgo = g_state[t & 1];
            float so0 = __ldcg(sgo + c0 * 8 + b);
            float so1 = __ldcg(sgo + (c0 + 1) * 8 + b);
            float n0 = 0.5f * so0 + 0.5f * ftanh(pre0);
            float n1 = 0.5f * so1 + 0.5f * ftanh(pre1);
            float* sn = g_state[(t & 1) ^ 1];
            __stcg(sn + c0 * 8 + b, n0);
            __stcg(sn + (c0 + 1) * 8 + b, n1);
            // state published -> release to own group counter, then out stores
            asm volatile("bar.sync 1, 64;" ::: "memory");
            if (tid == 0) {
                asm volatile("red.release.gpu.global.add.u32 [%0], %1;"
                             :: "l"(&g_cnt[grp * 64]), "r"(1u) : "memory");
            }
            float2 ov;                              // PowerIndex: even col squared
            ov.x = n0 * n0;
            ov.y = n1;
            *(float2*)(out + ((size_t)(b * TT + t)) * OUTF + DD + c0) = ov;
        }
    }
}

__global__ void copy_inputs_kernel(const float4* __restrict__ in, float* __restrict__ out) {
    int idx = blockIdx.x * blockDim.x + threadIdx.x;
    if (idx < BB * TT * DD / 4) {
        int bt = idx >> 5;  // 32 float4 per (b,t) row
        int q = idx & 31;
        float4 v = in[idx];
        *(float4*)(out + (size_t)bt * OUTF + q * 4) = v;
    }
}

extern "C" void kernel_launch(void* const* d_in, const int* in_sizes, int n_in,
                              void* d_out, int out_size) {
    const float* inputs = (const float*)d_in[0];
    const float* w_in   = (const float*)d_in[1];
    const float* b_in   = (const float*)d_in[2];
    const float* w_res  = (const float*)d_in[3];
    float* out = (float*)d_out;

    cudaFuncSetAttribute(esn_kernel, cudaFuncAttributeMaxDynamicSharedMemorySize, SMEM_BYTES);

    copy_inputs_kernel<<<(BB * TT * DD / 4 + 255) / 256, 256>>>((const float4*)inputs, out);
    esn_kernel<<<NCTA, NTHR, SMEM_BYTES>>>(inputs, w_in, b_in, w_res, out);
}

// round 16
// speedup vs baseline: 1.2050x; 1.2050x over previous
#include <cuda_runtime.h>
#include <math.h>

#define BB 8
#define TT 1024
#define DD 128
#define UU 2048
#define OUTF (DD + UU)
#define NCTA 128
#define COLS 16
#define NTHR 512
#define NWARP 16

typedef unsigned long long ull;

// SMEM layout (floats)
#define W_FLOATS   (UU * COLS)    // 32768  w_res slice, 64B rows, chunk-swizzled
#define S_FLOATS   (UU * BB)      // 16384  state, 16B-granule swizzled
#define WI_FLOATS  (DD * COLS)    // 2048   w_in slice, same swizzle
#define BI_FLOATS  16
#define RED_ULL    (NWARP * 64)   // [16 warps][64 og] f32x2 partials
#define SMEM_FLOATS (W_FLOATS + S_FLOATS + WI_FLOATS + BI_FLOATS + RED_ULL * 2)
#define SMEM_BYTES  (SMEM_FLOATS * 4)   // ~213 KB < 227 KB

__device__ float g_state[2][UU * BB];   // ping-pong state, linear [k][b]
__device__ unsigned g_bar_count;        // init barrier
__device__ unsigned g_bar_gen;          // monotone across replays
__device__ unsigned g_step_count;       // 1 release per CTA per step

__device__ __forceinline__ void cp16(unsigned dst, const void* src) {
    asm volatile("cp.async.cg.shared.global [%0], [%1], 16;" :: "r"(dst), "l"(src));
}
__device__ __forceinline__ void cp_commit() { asm volatile("cp.async.commit_group;"); }
template <int N>
__device__ __forceinline__ void cp_wait() {
    asm volatile("cp.async.wait_group %0;" :: "n"(N));
}
// packed fp32x2 ops — ptxas never emits these from C++
__device__ __forceinline__ void ffma2(ull& acc, ull a, ull b) {
    asm("fma.rn.f32x2 %0, %1, %2, %0;" : "+l"(acc) : "l"(a), "l"(b));
}
__device__ __forceinline__ ull dup2(float x) {
    ull r;
    unsigned xi = __float_as_uint(x);
    asm("mov.b64 %0, {%1, %1};" : "=l"(r) : "r"(xi));
    return r;
}
__device__ __forceinline__ ull padd2(ull a, ull b) {
    ull r;
    asm("add.rn.f32x2 %0, %1, %2;" : "=l"(r) : "l"(a), "l"(b));
    return r;
}
__device__ __forceinline__ ull bfly2(ull v, int m) {
    unsigned lo = (unsigned)v, hi = (unsigned)(v >> 32);
    lo = __shfl_xor_sync(0xffffffffu, lo, m);
    hi = __shfl_xor_sync(0xffffffffu, hi, m);
    ull r;
    asm("mov.b64 %0, {%1, %2};" : "=l"(r) : "r"(lo), "r"(hi));
    return r;
}

// init-only grid barrier (proven pattern)
__device__ __forceinline__ void grid_barrier_init() {
    __syncthreads();
    if (threadIdx.x == 0) {
        __threadfence();
        unsigned gen;
        asm volatile("ld.acquire.gpu.u32 %0, [%1];" : "=r"(gen) : "l"(&g_bar_gen));
        if (atomicAdd(&g_bar_count, 1) == NCTA - 1) {
            g_bar_count = 0;
            asm volatile("st.release.gpu.u32 [%0], %1;" :: "l"(&g_bar_gen), "r"(gen + 1)
                         : "memory");
        } else {
            unsigned cur;
            do {
                asm volatile("ld.acquire.gpu.u32 %0, [%1];" : "=r"(cur) : "l"(&g_bar_gen));
                if (cur != gen) break;
                __nanosleep(32);
            } while (true);
        }
    }
    __syncthreads();
}

__global__ void __launch_bounds__(NTHR, 1)
esn_kernel(const float* __restrict__ inputs, const float* __restrict__ w_in_g,
           const float* __restrict__ b_in_g, const float* __restrict__ w_res_g,
           float* __restrict__ out) {
    extern __shared__ float smem[];
    float* w_sh  = smem;                    // [2048][16] chunk-swizzled
    float* s_sh  = w_sh + W_FLOATS;         // [2048][8] granule-swizzled
    float* wi_sh = s_sh + S_FLOATS;         // [128][16] chunk-swizzled
    float* bi_sh = wi_sh + WI_FLOATS;       // [16]
    ull* red = (ull*)(bi_sh + BI_FLOATS);   // [16 warps][64]

    const int tid = threadIdx.x;
    const int cta = blockIdx.x;
    const int col0 = cta * COLS;

    if (cta == 0 && tid == 0) g_step_count = 0;   // fresh epoch per launch/replay

    // Stage w_res slice; 16B chunk c of row r stored at position c ^ ((r>>1)&3)
    for (int r = tid; r < UU; r += NTHR) {
        const float4* src = (const float4*)(w_res_g + (size_t)r * UU + col0);
        int m = (r >> 1) & 3;
        float4* dst = (float4*)(w_sh + r * COLS);
        dst[0 ^ m] = src[0]; dst[1 ^ m] = src[1];
        dst[2 ^ m] = src[2]; dst[3 ^ m] = src[3];
    }
    if (tid < DD) {
        int r = tid;
        const float4* src = (const float4*)(w_in_g + (size_t)r * UU + col0);
        int m = (r >> 1) & 3;
        float4* dst = (float4*)(wi_sh + r * COLS);
        dst[0 ^ m] = src[0]; dst[1 ^ m] = src[1];
        dst[2 ^ m] = src[2]; dst[3 ^ m] = src[3];
    }
    if (tid < COLS) bi_sh[tid] = b_in_g[col0 + tid];

    // Zero initial state (buffer 0)
    for (int i = cta * NTHR + tid; i < UU * BB; i += NCTA * NTHR) g_state[0][i] = 0.0f;

    grid_barrier_init();

    // Decomposition: paired lanes share a k-slice (state reads broadcast);
    // jh = column half (8 cols each). Thread rows: ks + 256*i.
    const int warp = tid >> 5;
    const int lane = tid & 31;
    const int jh = lane & 1;
    const int ks = (warp << 4) + (lane >> 1);     // 0..255
    const int mk = (ks >> 1) & 3;                 // weight chunk-swizzle key
    const unsigned w_off0 = (unsigned)(4 * ks + ((2 * jh) ^ mk)) * 16;
    const unsigned w_off1 = (unsigned)(4 * ks + ((2 * jh + 1) ^ mk)) * 16;
    const unsigned gA = 2 * ks, gB = 2 * ks + 1;  // state granules of row ks (i=0)
    const unsigned sA_off = (gA ^ ((gA >> 3) & 1)) * 16;
    const unsigned sB_off = (gB ^ ((gB >> 3) & 1)) * 16;
    // butterfly landing map: lane bit1->+16, bit2->+8, bit3->+4, bit4->+2
    const int base = (((lane >> 1) & 1) << 4) | (((lane >> 2) & 1) << 3) |
                     (((lane >> 3) & 1) << 2) | (((lane >> 4) & 1) << 1);
    const unsigned s_base = (unsigned)__cvta_generic_to_shared(s_sh);

    for (int t = 0; t < TT; ++t) {
        // x_t for proj rows (ks<128): independent of state, in flight over the gate
        float xv[8];
        if (ks < DD) {
#pragma unroll
            for (int b = 0; b < 8; ++b)
                xv[b] = __ldg(inputs + ((size_t)(b * TT + t)) * DD + ks);
        }

        // Step gate: all 128 CTAs released step t-1 (1 release per CTA)
        if (tid == 0) {
            const unsigned target = 128u * (unsigned)t;
            unsigned v;
            do {
                asm volatile("ld.acquire.gpu.global.u32 %0, [%1];"
                             : "=r"(v) : "l"(&g_step_count));
            } while (v < target);
        }
        __syncthreads();

        // Broadcast state: 4 chunks x 16KB; granule g stored at g ^ ((g>>3)&1)
        const float* sg = g_state[t & 1];
#pragma unroll
        for (int c = 0; c < 4; ++c) {
            int g0 = c * 1024 + tid;
            cp16(s_base + ((unsigned)(g0 ^ ((g0 >> 3) & 1)) << 4), sg + g0 * 4);
            int g1 = g0 + 512;
            cp16(s_base + ((unsigned)(g1 ^ ((g1 >> 3) & 1)) << 4), sg + g1 * 4);
            cp_commit();
        }

        ull acc[8][4];
#pragma unroll
        for (int a1 = 0; a1 < 8; ++a1)
#pragma unroll
            for (int a2 = 0; a2 < 4; ++a2) acc[a1][a2] = 0ULL;

        // Input projection (overlaps chunk-0 flight); wi row = ks, same offsets
        if (ks < DD) {
            ulonglong2 u0 = *(const ulonglong2*)((const char*)wi_sh + w_off0);
            ulonglong2 u1 = *(const ulonglong2*)((const char*)wi_sh + w_off1);
#pragma unroll
            for (int b = 0; b < 8; ++b) {
                ull d = dup2(xv[b]);
                ffma2(acc[b][0], u0.x, d); ffma2(acc[b][1], u0.y, d);
                ffma2(acc[b][2], u1.x, d); ffma2(acc[b][3], u1.y, d);
            }
        }

#define ROW(i)                                                                          \
    {                                                                                   \
        float4 sA = *(const float4*)((const char*)s_sh + sA_off + (i) * 8192);          \
        float4 sB = *(const float4*)((const char*)s_sh + sB_off + (i) * 8192);          \
        ulonglong2 u0 = *(const ulonglong2*)((const char*)w_sh + w_off0 + (i) * 16384); \
        ulonglong2 u1 = *(const ulonglong2*)((const char*)w_sh + w_off1 + (i) * 16384); \
        ull d;                                                                          \
        d = dup2(sA.x);                                                                 \
        ffma2(acc[0][0], u0.x, d); ffma2(acc[0][1], u0.y, d);                           \
        ffma2(acc[0][2], u1.x, d); ffma2(acc[0][3], u1.y, d);                           \
        d = dup2(sA.y);                                                                 \
        ffma2(acc[1][0], u0.x, d); ffma2(acc[1][1], u0.y, d);                           \
        ffma2(acc[1][2], u1.x, d); ffma2(acc[1][3], u1.y, d);                           \
        d = dup2(sA.z);                                                                 \
        ffma2(acc[2][0], u0.x, d); ffma2(acc[2][1], u0.y, d);                           \
        ffma2(acc[2][2], u1.x, d); ffma2(acc[2][3], u1.y, d);                           \
        d = dup2(sA.w);                                                                 \
        ffma2(acc[3][0], u0.x, d); ffma2(acc[3][1], u0.y, d);                           \
        ffma2(acc[3][2], u1.x, d); ffma2(acc[3][3], u1.y, d);                           \
        d = dup2(sB.x);                                                                 \
        ffma2(acc[4][0], u0.x, d); ffma2(acc[4][1], u0.y, d);                           \
        ffma2(acc[4][2], u1.x, d); ffma2(acc[4][3], u1.y, d);                           \
        d = dup2(sB.y);                                                                 \
        ffma2(acc[5][0], u0.x, d); ffma2(acc[5][1], u0.y, d);                           \
        ffma2(acc[5][2], u1.x, d); ffma2(acc[5][3], u1.y, d);                           \
        d = dup2(sB.z);                                                                 \
        ffma2(acc[6][0], u0.x, d); ffma2(acc[6][1], u0.y, d);                           \
        ffma2(acc[6][2], u1.x, d); ffma2(acc[6][3], u1.y, d);                           \
        d = dup2(sB.w);                                                                 \
        ffma2(acc[7][0], u0.x, d); ffma2(acc[7][1], u0.y, d);                           \
        ffma2(acc[7][2], u1.x, d); ffma2(acc[7][3], u1.y, d);                           \
    }

        // Pipelined dot: chunk c holds rows [512c, 512c+512) = i = 2c, 2c+1
        cp_wait<3>(); __syncthreads();
        ROW(0) ROW(1)
        cp_wait<2>(); __syncthreads();
        ROW(2) ROW(3)
        cp_wait<1>(); __syncthreads();
        ROW(4) ROW(5)
        cp_wait<0>(); __syncthreads();
        ROW(6) ROW(7)
#undef ROW

        // 4-level butterfly over masks 2,4,8,16 (mask-1 partner owns the other
        // column half, not summed). Lane ends with og (jh, base), (jh, base+1).
        {
            ull* A = &acc[0][0];
#pragma unroll
            for (int lev = 0; lev < 4; ++lev) {
                const int mm = 2 << lev;
                const int n = 16 >> lev;
                const bool up = (lane & mm) != 0;
#pragma unroll
                for (int q = 0; q < n; ++q) {
                    ull send = up ? A[q] : A[q + n];
                    ull recv = bfly2(send, mm);
                    ull keep = up ? A[q + n] : A[q];
                    A[q] = padd2(keep, recv);
                }
            }
            red[warp * 64 + jh * 32 + base] = A[0];
            red[warp * 64 + jh * 32 + base + 1] = A[1];
        }
        __syncthreads();

        // Final reduce over 16 warps + epilogue (64 threads)
        if (tid < 64) {
            ull v = red[tid];
#pragma unroll
            for (int w = 1; w < NWARP; ++w) v = padd2(v, red[w * 64 + tid]);
            const int jh2 = tid >> 5;
            const int a = tid & 31;
            const int b = a >> 2;
            const int p = a & 3;
            const int jl = jh2 * 8 + 2 * p;
            const int c0 = col0 + jl;
            float pre0 = __uint_as_float((unsigned)v) + bi_sh[jl];
            float pre1 = __uint_as_float((unsigned)(v >> 32)) + bi_sh[jl + 1];
            unsigned G0 = (unsigned)(2 * c0 + (b >> 2));
            unsigned G1 = G0 + 2;
            float so0 = s_sh[(G0 ^ ((G0 >> 3) & 1)) * 4 + (b & 3)];
            float so1 = s_sh[(G1 ^ ((G1 >> 3) & 1)) * 4 + (b & 3)];
            float n0 = 0.5f * so0 + 0.5f * tanhf(pre0);
            float n1 = 0.5f * so1 + 0.5f * tanhf(pre1);
            float* sn = g_state[(t & 1) ^ 1];      // linear layout in global
            __stcg(sn + c0 * 8 + b, n0);
            __stcg(sn + (c0 + 1) * 8 + b, n1);
            float2 ov;                              // PowerIndex: even col squared
            ov.x = n0 * n0;
            ov.y = n1;
            *(float2*)(out + ((size_t)(b * TT + t)) * OUTF + DD + c0) = ov;
        }
        __syncthreads();   // epilogue done before release; protects s_sh reuse

        // Single cumulative release per CTA (bar orders all 64 threads' stores)
        if (tid == 0) {
            asm volatile("red.release.gpu.global.add.u32 [%0], %1;"
                         :: "l"(&g_step_count), "r"(1u) : "memory");
        }
    }
}

__global__ void copy_inputs_kernel(const float4* __restrict__ in, float* __restrict__ out) {
    int idx = blockIdx.x * blockDim.x + threadIdx.x;
    if (idx < BB * TT * DD / 4) {
        int bt = idx >> 5;  // 32 float4 per (b,t) row
        int q = idx & 31;
        float4 v = in[idx];
        *(float4*)(out + (size_t)bt * OUTF + q * 4) = v;
    }
}

extern "C" void kernel_launch(void* const* d_in, const int* in_sizes, int n_in,
                              void* d_out, int out_size) {
    const float* inputs = (const float*)d_in[0];
    const float* w_in   = (const float*)d_in[1];
    const float* b_in   = (const float*)d_in[2];
    const float* w_res  = (const float*)d_in[3];
    float* out = (float*)d_out;

    cudaFuncSetAttribute(esn_kernel, cudaFuncAttributeMaxDynamicSharedMemorySize, SMEM_BYTES);

    copy_inputs_kernel<<<(BB * TT * DD / 4 + 255) / 256, 256>>>((const float4*)inputs, out);
    esn_kernel<<<NCTA, NTHR, SMEM_BYTES>>>(inputs, w_in, b_in, w_res, out);
}

// round 17
// speedup vs baseline: 1.2085x; 1.0029x over previous
#include <cuda_runtime.h>
#include <math.h>

#define BB 8
#define TT 1024
#define DD 128
#define UU 2048
#define OUTF (DD + UU)
#define NCTA 128
#define COLS 16
#define NTHR 512
#define NWARP 16

typedef unsigned long long ull;

// SMEM layout (floats)
#define W_FLOATS   (UU * COLS)    // 32768  w_res slice, 64B rows, chunk-swizzled
#define S_FLOATS   (UU * BB)      // 16384  state, 16B-granule swizzled
#define WI_FLOATS  (DD * COLS)    // 2048   w_in slice, same swizzle
#define BI_FLOATS  16
#define RED_ULL    (NWARP * 64)   // [16 warps][64 og] f32x2 partials
#define SMEM_FLOATS (W_FLOATS + S_FLOATS + WI_FLOATS + BI_FLOATS + RED_ULL * 2)
#define SMEM_BYTES  (SMEM_FLOATS * 4)   // ~213 KB < 227 KB

__device__ float g_state[2][UU * BB];   // ping-pong state, linear [k][b]
__device__ unsigned g_bar_count;        // init barrier
__device__ unsigned g_bar_gen;          // monotone across replays
__device__ unsigned g_step_count;       // 1 release per CTA per step

__device__ __forceinline__ void cp16(unsigned dst, const void* src) {
    asm volatile("cp.async.cg.shared.global [%0], [%1], 16;" :: "r"(dst), "l"(src));
}
__device__ __forceinline__ void cp_commit() { asm volatile("cp.async.commit_group;"); }
template <int N>
__device__ __forceinline__ void cp_wait() {
    asm volatile("cp.async.wait_group %0;" :: "n"(N));
}
// packed fp32x2 ops — ptxas never emits these from C++
__device__ __forceinline__ void ffma2(ull& acc, ull a, ull b) {
    asm("fma.rn.f32x2 %0, %1, %2, %0;" : "+l"(acc) : "l"(a), "l"(b));
}
__device__ __forceinline__ ull dup2(float x) {
    ull r;
    unsigned xi = __float_as_uint(x);
    asm("mov.b64 %0, {%1, %1};" : "=l"(r) : "r"(xi));
    return r;
}
__device__ __forceinline__ ull padd2(ull a, ull b) {
    ull r;
    asm("add.rn.f32x2 %0, %1, %2;" : "=l"(r) : "l"(a), "l"(b));
    return r;
}
__device__ __forceinline__ ull bfly2(ull v, int m) {
    unsigned lo = (unsigned)v, hi = (unsigned)(v >> 32);
    lo = __shfl_xor_sync(0xffffffffu, lo, m);
    hi = __shfl_xor_sync(0xffffffffu, hi, m);
    ull r;
    asm("mov.b64 %0, {%1, %2};" : "=l"(r) : "r"(lo), "r"(hi));
    return r;
}

// init-only grid barrier (proven pattern)
__device__ __forceinline__ void grid_barrier_init() {
    __syncthreads();
    if (threadIdx.x == 0) {
        __threadfence();
        unsigned gen;
        asm volatile("ld.acquire.gpu.u32 %0, [%1];" : "=r"(gen) : "l"(&g_bar_gen));
        if (atomicAdd(&g_bar_count, 1) == NCTA - 1) {
            g_bar_count = 0;
            asm volatile("st.release.gpu.u32 [%0], %1;" :: "l"(&g_bar_gen), "r"(gen + 1)
                         : "memory");
        } else {
            unsigned cur;
            do {
                asm volatile("ld.acquire.gpu.u32 %0, [%1];" : "=r"(cur) : "l"(&g_bar_gen));
                if (cur != gen) break;
                __nanosleep(32);
            } while (true);
        }
    }
    __syncthreads();
}

__global__ void __launch_bounds__(NTHR, 1)
esn_kernel(const float* __restrict__ inputs, const float* __restrict__ w_in_g,
           const float* __restrict__ b_in_g, const float* __restrict__ w_res_g,
           float* __restrict__ out) {
    extern __shared__ float smem[];
    float* w_sh  = smem;                    // [2048][16] chunk-swizzled
    float* s_sh  = w_sh + W_FLOATS;         // [2048][8] granule-swizzled
    float* wi_sh = s_sh + S_FLOATS;         // [128][16] chunk-swizzled
    float* bi_sh = wi_sh + WI_FLOATS;       // [16]
    ull* red = (ull*)(bi_sh + BI_FLOATS);   // [16 warps][64]

    const int tid = threadIdx.x;
    const int cta = blockIdx.x;
    const int col0 = cta * COLS;

    if (cta == 0 && tid == 0) g_step_count = 0;   // fresh epoch per launch/replay

    // Stage w_res slice; 16B chunk c of row r stored at position c ^ ((r>>1)&3)
    for (int r = tid; r < UU; r += NTHR) {
        const float4* src = (const float4*)(w_res_g + (size_t)r * UU + col0);
        int m = (r >> 1) & 3;
        float4* dst = (float4*)(w_sh + r * COLS);
        dst[0 ^ m] = src[0]; dst[1 ^ m] = src[1];
        dst[2 ^ m] = src[2]; dst[3 ^ m] = src[3];
    }
    if (tid < DD) {
        int r = tid;
        const float4* src = (const float4*)(w_in_g + (size_t)r * UU + col0);
        int m = (r >> 1) & 3;
        float4* dst = (float4*)(wi_sh + r * COLS);
        dst[0 ^ m] = src[0]; dst[1 ^ m] = src[1];
        dst[2 ^ m] = src[2]; dst[3 ^ m] = src[3];
    }
    if (tid < COLS) bi_sh[tid] = b_in_g[col0 + tid];

    // Zero initial state (buffer 0)
    for (int i = cta * NTHR + tid; i < UU * BB; i += NCTA * NTHR) g_state[0][i] = 0.0f;

    grid_barrier_init();

    // Decomposition: paired lanes share a k-slice (state reads broadcast);
    // jh = column half (8 cols each). Thread rows: ks + 256*i.
    const int warp = tid >> 5;
    const int lane = tid & 31;
    const int jh = lane & 1;
    const int ks = (warp << 4) + (lane >> 1);     // 0..255
    const int mk = (ks >> 1) & 3;                 // weight chunk-swizzle key
    const unsigned w_off0 = (unsigned)(4 * ks + ((2 * jh) ^ mk)) * 16;
    const unsigned w_off1 = (unsigned)(4 * ks + ((2 * jh + 1) ^ mk)) * 16;
    const unsigned gA = 2 * ks, gB = 2 * ks + 1;  // state granules of row ks (i=0)
    const unsigned sA_off = (gA ^ ((gA >> 3) & 1)) * 16;
    const unsigned sB_off = (gB ^ ((gB >> 3) & 1)) * 16;
    // butterfly landing map: lane bit1->+16, bit2->+8, bit3->+4, bit4->+2
    const int base = (((lane >> 1) & 1) << 4) | (((lane >> 2) & 1) << 3) |
                     (((lane >> 3) & 1) << 2) | (((lane >> 4) & 1) << 1);
    const unsigned s_base = (unsigned)__cvta_generic_to_shared(s_sh);

    for (int t = 0; t < TT; ++t) {
        // x_t for proj rows (ks<128): independent of state, in flight over the gate
        float xv[8];
        if (ks < DD) {
#pragma unroll
            for (int b = 0; b < 8; ++b)
                xv[b] = __ldg(inputs + ((size_t)(b * TT + t)) * DD + ks);
        }

        // Step gate: all 128 CTAs released step t-1 (1 release per CTA)
        if (tid == 0) {
            const unsigned target = 128u * (unsigned)t;
            unsigned v;
            do {
                asm volatile("ld.acquire.gpu.global.u32 %0, [%1];"
                             : "=r"(v) : "l"(&g_step_count));
            } while (v < target);
        }
        __syncthreads();

        // Broadcast state: 4 chunks x 16KB; granule g stored at g ^ ((g>>3)&1)
        const float* sg = g_state[t & 1];
#pragma unroll
        for (int c = 0; c < 4; ++c) {
            int g0 = c * 1024 + tid;
            cp16(s_base + ((unsigned)(g0 ^ ((g0 >> 3) & 1)) << 4), sg + g0 * 4);
            int g1 = g0 + 512;
            cp16(s_base + ((unsigned)(g1 ^ ((g1 >> 3) & 1)) << 4), sg + g1 * 4);
            cp_commit();
        }

        ull acc[8][4];
#pragma unroll
        for (int a1 = 0; a1 < 8; ++a1)
#pragma unroll
            for (int a2 = 0; a2 < 4; ++a2) acc[a1][a2] = 0ULL;

        // Input projection (overlaps chunk-0 flight); wi row = ks, same offsets
        if (ks < DD) {
            ulonglong2 u0 = *(const ulonglong2*)((const char*)wi_sh + w_off0);
            ulonglong2 u1 = *(const ulonglong2*)((const char*)wi_sh + w_off1);
#pragma unroll
            for (int b = 0; b < 8; ++b) {
                ull d = dup2(xv[b]);
                ffma2(acc[b][0], u0.x, d); ffma2(acc[b][1], u0.y, d);
                ffma2(acc[b][2], u1.x, d); ffma2(acc[b][3], u1.y, d);
            }
        }

#define ROW(i)                                                                          \
    {                                                                                   \
        float4 sA = *(const float4*)((const char*)s_sh + sA_off + (i) * 8192);          \
        float4 sB = *(const float4*)((const char*)s_sh + sB_off + (i) * 8192);          \
        ulonglong2 u0 = *(const ulonglong2*)((const char*)w_sh + w_off0 + (i) * 16384); \
        ulonglong2 u1 = *(const ulonglong2*)((const char*)w_sh + w_off1 + (i) * 16384); \
        ull d;                                                                          \
        d = dup2(sA.x);                                                                 \
        ffma2(acc[0][0], u0.x, d); ffma2(acc[0][1], u0.y, d);                           \
        ffma2(acc[0][2], u1.x, d); ffma2(acc[0][3], u1.y, d);                           \
        d = dup2(sA.y);                                                                 \
        ffma2(acc[1][0], u0.x, d); ffma2(acc[1][1], u0.y, d);                           \
        ffma2(acc[1][2], u1.x, d); ffma2(acc[1][3], u1.y, d);                           \
        d = dup2(sA.z);                                                                 \
        ffma2(acc[2][0], u0.x, d); ffma2(acc[2][1], u0.y, d);                           \
        ffma2(acc[2][2], u1.x, d); ffma2(acc[2][3], u1.y, d);                           \
        d = dup2(sA.w);                                                                 \
        ffma2(acc[3][0], u0.x, d); ffma2(acc[3][1], u0.y, d);                           \
        ffma2(acc[3][2], u1.x, d); ffma2(acc[3][3], u1.y, d);                           \
        d = dup2(sB.x);                                                                 \
        ffma2(acc[4][0], u0.x, d); ffma2(acc[4][1], u0.y, d);                           \
        ffma2(acc[4][2], u1.x, d); ffma2(acc[4][3], u1.y, d);                           \
        d = dup2(sB.y);                                                                 \
        ffma2(acc[5][0], u0.x, d); ffma2(acc[5][1], u0.y, d);                           \
        ffma2(acc[5][2], u1.x, d); ffma2(acc[5][3], u1.y, d);                           \
        d = dup2(sB.z);                                                                 \
        ffma2(acc[6][0], u0.x, d); ffma2(acc[6][1], u0.y, d);                           \
        ffma2(acc[6][2], u1.x, d); ffma2(acc[6][3], u1.y, d);                           \
        d = dup2(sB.w);                                                                 \
        ffma2(acc[7][0], u0.x, d); ffma2(acc[7][1], u0.y, d);                           \
        ffma2(acc[7][2], u1.x, d); ffma2(acc[7][3], u1.y, d);                           \
    }

        // Pipelined dot: chunk c holds rows [512c, 512c+512) = i = 2c, 2c+1
        cp_wait<3>(); __syncthreads();
        ROW(0) ROW(1)
        cp_wait<2>(); __syncthreads();
        ROW(2) ROW(3)
        cp_wait<1>(); __syncthreads();
        ROW(4) ROW(5)
        cp_wait<0>(); __syncthreads();
        ROW(6) ROW(7)
#undef ROW

        // 4-level butterfly over masks 2,4,8,16 (mask-1 partner owns the other
        // column half, not summed). Lane ends with og (jh, base), (jh, base+1).
        {
            ull* A = &acc[0][0];
#pragma unroll
            for (int lev = 0; lev < 4; ++lev) {
                const int mm = 2 << lev;
                const int n = 16 >> lev;
                const bool up = (lane & mm) != 0;
#pragma unroll
                for (int q = 0; q < n; ++q) {
                    ull send = up ? A[q] : A[q + n];
                    ull recv = bfly2(send, mm);
                    ull keep = up ? A[q + n] : A[q];
                    A[q] = padd2(keep, recv);
                }
            }
            red[warp * 64 + jh * 32 + base] = A[0];
            red[warp * 64 + jh * 32 + base + 1] = A[1];
        }
        __syncthreads();

        // Final reduce over 16 warps + epilogue (64 threads)
        if (tid < 64) {
            ull v = red[tid];
#pragma unroll
            for (int w = 1; w < NWARP; ++w) v = padd2(v, red[w * 64 + tid]);
            const int jh2 = tid >> 5;
            const int a = tid & 31;
            const int b = a >> 2;
            const int p = a & 3;
            const int jl = jh2 * 8 + 2 * p;
            const int c0 = col0 + jl;
            float pre0 = __uint_as_float((unsigned)v) + bi_sh[jl];
            float pre1 = __uint_as_float((unsigned)(v >> 32)) + bi_sh[jl + 1];
            unsigned G0 = (unsigned)(2 * c0 + (b >> 2));
            unsigned G1 = G0 + 2;
            float so0 = s_sh[(G0 ^ ((G0 >> 3) & 1)) * 4 + (b & 3)];
            float so1 = s_sh[(G1 ^ ((G1 >> 3) & 1)) * 4 + (b & 3)];
            float n0 = 0.5f * so0 + 0.5f * tanhf(pre0);
            float n1 = 0.5f * so1 + 0.5f * tanhf(pre1);
            float* sn = g_state[(t & 1) ^ 1];      // linear layout in global
            __stcg(sn + c0 * 8 + b, n0);
            __stcg(sn + (c0 + 1) * 8 + b, n1);
            float2 ov;                              // PowerIndex: even col squared
            ov.x = n0 * n0;
            ov.y = n1;
            *(float2*)(out + ((size_t)(b * TT + t)) * OUTF + DD + c0) = ov;
        }
        __syncthreads();   // epilogue done before release; protects s_sh reuse

        // Single cumulative release per CTA (bar orders all 64 threads' stores)
        if (tid == 0) {
            asm volatile("red.release.gpu.global.add.u32 [%0], %1;"
                         :: "l"(&g_step_count), "r"(1u) : "memory");
        }
    }
}

__global__ void copy_inputs_kernel(const float4* __restrict__ in, float* __restrict__ out) {
    int idx = blockIdx.x * blockDim.x + threadIdx.x;
    if (idx < BB * TT * DD / 4) {
        int bt = idx >> 5;  // 32 float4 per (b,t) row
        int q = idx & 31;
        float4 v = in[idx];
        *(float4*)(out + (size_t)bt * OUTF + q * 4) = v;
    }
}

extern "C" void kernel_launch(void* const* d_in, const int* in_sizes, int n_in,
                              void* d_out, int out_size) {
    const float* inputs = (const float*)d_in[0];
    const float* w_in   = (const float*)d_in[1];
    const float* b_in   = (const float*)d_in[2];
    const float* w_res  = (const float*)d_in[3];
    float* out = (float*)d_out;

    cudaFuncSetAttribute(esn_kernel, cudaFuncAttributeMaxDynamicSharedMemorySize, SMEM_BYTES);

    copy_inputs_kernel<<<(BB * TT * DD / 4 + 255) / 256, 256>>>((const float4*)inputs, out);
    esn_kernel<<<NCTA, NTHR, SMEM_BYTES>>>(inputs, w_in, b_in, w_res, out);
}